// round 14
// baseline (speedup 1.0000x reference)
#include <cuda_runtime.h>
#include <cuda_fp16.h>
#include <cstdint>

#define SWZ(o) ((o) ^ (((o) >> 3) & 0x70))
// exp(s/8) = 2^(s * QSCALE_LOG):  folded into q at the QKV epilogue
#define QSCALE_LOG 0.18033688011112042f   // 0.125 * log2(e)

// fp16 staging / intermediate buffers
__device__ __align__(16) __half g_xh[8388608];    // X as half [8192][1024]
__device__ __align__(16) __half g_whq[1048576];
__device__ __align__(16) __half g_whk[1048576];
__device__ __align__(16) __half g_whv[1048576];
__device__ __align__(16) __half g_who[1048576];
__device__ __align__(16) __half g_qh[8388608];    // [B*H][2048][64]  (q pre-scaled)
__device__ __align__(16) __half g_kh[8388608];
__device__ __align__(16) __half g_vh[8388608];
__device__ __align__(16) __half g_oh[8388608];    // attn out [8192][1024]

// ---------------------------------------------------------------------------
// helpers
// ---------------------------------------------------------------------------
__device__ __forceinline__ uint32_t smem_u32(const void* p) {
    uint32_t a;
    asm("{ .reg .u64 t; cvta.to.shared.u64 t, %1; cvt.u32.u64 %0, t; }"
        : "=r"(a) : "l"(p));
    return a;
}
__device__ __forceinline__ void cpa16(uint32_t s, const void* g) {
    asm volatile("cp.async.cg.shared.global [%0], [%1], 16;"
                 :: "r"(s), "l"(g) : "memory");
}
__device__ __forceinline__ void cp_commit() {
    asm volatile("cp.async.commit_group;" ::: "memory");
}
template <int N>
__device__ __forceinline__ void cp_wait() {
    asm volatile("cp.async.wait_group %0;" :: "n"(N) : "memory");
}
__device__ __forceinline__ void ldm_x4(uint32_t* r, uint32_t addr) {
    asm volatile("ldmatrix.sync.aligned.m8n8.x4.shared.b16 {%0,%1,%2,%3}, [%4];"
                 : "=r"(r[0]), "=r"(r[1]), "=r"(r[2]), "=r"(r[3]) : "r"(addr));
}
__device__ __forceinline__ void ldm_x4t(uint32_t* r, uint32_t addr) {
    asm volatile("ldmatrix.sync.aligned.m8n8.x4.trans.shared.b16 {%0,%1,%2,%3}, [%4];"
                 : "=r"(r[0]), "=r"(r[1]), "=r"(r[2]), "=r"(r[3]) : "r"(addr));
}
// D(f32) += A(f16 m16k16) * B(f16 col-major k16n8)
__device__ __forceinline__ void mma_f16(float* c, const uint32_t* a, const uint32_t* b) {
    asm volatile(
        "mma.sync.aligned.m16n8k16.row.col.f32.f16.f16.f32 "
        "{%0,%1,%2,%3}, {%4,%5,%6,%7}, {%8,%9}, {%0,%1,%2,%3};"
        : "+f"(c[0]), "+f"(c[1]), "+f"(c[2]), "+f"(c[3])
        : "r"(a[0]), "r"(a[1]), "r"(a[2]), "r"(a[3]), "r"(b[0]), "r"(b[1]));
}
__device__ __forceinline__ uint32_t packh2(float a, float b) {
    __half2 h = __floats2half2_rn(a, b);
    return *reinterpret_cast<uint32_t*>(&h);
}
// saturating pack: clamps to +-65504 instead of producing inf
__device__ __forceinline__ uint32_t packh2s(float a, float b) {
    uint32_t r;
    asm("cvt.rn.satfinite.f16x2.f32 %0, %1, %2;" : "=r"(r) : "f"(b), "f"(a));
    return r;
}
// 2^x on both f16 halves (one MUFU op for two exps)
__device__ __forceinline__ void h2exp2(uint32_t& v) {
    asm("ex2.approx.f16x2 %0, %0;" : "+r"(v));
}

// ---------------------------------------------------------------------------
// f32 -> f16 pre-pass for X and the 4 weight matrices (one launch)
// ---------------------------------------------------------------------------
__global__ __launch_bounds__(256) void f2h_multi(
    const float* __restrict__ x,  const float* __restrict__ wq,
    const float* __restrict__ wk, const float* __restrict__ wv,
    const float* __restrict__ wo)
{
    int i = blockIdx.x * 256 + threadIdx.x;   // float4 index, total 3145728
    const float4* s;
    __half* d;
    int off;
    if (i < 2097152) { s = (const float4*)x; d = g_xh; off = i; }
    else {
        int r = i - 2097152;
        int w = r >> 18;
        off = r & 262143;
        s = (const float4*)(w == 0 ? wq : w == 1 ? wk : w == 2 ? wv : wo);
        d = (w == 0) ? g_whq : (w == 1) ? g_whk : (w == 2) ? g_whv : g_who;
    }
    float4 v = s[off];
    uint2 u;
    u.x = packh2(v.x, v.y);
    u.y = packh2(v.z, v.w);
    *reinterpret_cast<uint2*>(d + (size_t)off * 4) = u;
}

// ---------------------------------------------------------------------------
// f16 MMA GEMM mainloop: C[128,128] = A * B^T, BK=64, 3-stage cp.async, one
// sync per k-iter, per-warp kk rotation.  8 warps = 4(m) x 2(n).
// ---------------------------------------------------------------------------
__device__ __forceinline__ void gemm_mainloop_f16(
    const __half* __restrict__ A, const __half* __restrict__ B,
    int m0, int n0, uint32_t sbase, float (&acc)[2][8][4])
{
    const int tid = threadIdx.x, lane = tid & 31, warp = tid >> 5;
    const int lr = lane & 7, lmat = lane >> 3;
    const int wm = (warp & 3) * 32, wn = (warp >> 2) * 64;
    const int srow = tid >> 3, sch = tid & 7;
    const int krot = warp & 3;

    const __half* ga[4];
    const __half* gb[4];
    uint32_t swo[4];
    #pragma unroll
    for (int j = 0; j < 4; j++) {
        int row = srow + j * 32;
        ga[j] = A + (size_t)(m0 + row) * 1024 + sch * 8;
        gb[j] = B + (size_t)(n0 + row) * 1024 + sch * 8;
        swo[j] = SWZ((uint32_t)(row * 128 + sch * 16));
    }
    #pragma unroll
    for (int a = 0; a < 2; a++)
        #pragma unroll
        for (int b = 0; b < 8; b++)
            #pragma unroll
            for (int r = 0; r < 4; r++) acc[a][b][r] = 0.f;

    auto ISSUE = [&](int s) {
        uint32_t ab = sbase + (s % 3) * 32768, bb = ab + 16384;
        #pragma unroll
        for (int j = 0; j < 4; j++) {
            cpa16(ab + swo[j], ga[j] + s * 64);
            cpa16(bb + swo[j], gb[j] + s * 64);
        }
        cp_commit();
    };

    ISSUE(0); ISSUE(1);
    for (int i = 0; i < 16; i++) {
        if (i + 1 < 16) cp_wait<1>();
        else            cp_wait<0>();
        __syncthreads();
        if (i + 2 < 16) ISSUE(i + 2);
        uint32_t ab = sbase + (i % 3) * 32768, bb = ab + 16384;
        #pragma unroll
        for (int kk0 = 0; kk0 < 4; kk0++) {
            const int kk = (kk0 + krot) & 3;     // per-warp phase stagger
            const int c0 = kk * 2;
            uint32_t a[2][4];
            #pragma unroll
            for (int mf = 0; mf < 2; mf++) {
                int row = wm + mf * 16 + lr + (lmat & 1) * 8;
                int ch  = c0 + (lmat >> 1);
                ldm_x4(a[mf], ab + SWZ((uint32_t)(row * 128 + ch * 16)));
            }
            #pragma unroll
            for (int q = 0; q < 4; q++) {
                uint32_t bq[4];
                int row = wn + q * 16 + lr + (lmat >> 1) * 8;
                int ch  = c0 + (lmat & 1);
                ldm_x4(bq, bb + SWZ((uint32_t)(row * 128 + ch * 16)));
                #pragma unroll
                for (int mf = 0; mf < 2; mf++) {
                    mma_f16(acc[mf][2 * q],     a[mf], bq);
                    mma_f16(acc[mf][2 * q + 1], a[mf], bq + 2);
                }
            }
        }
    }
}

// ---------------------------------------------------------------------------
// QKV projection (+RoPE).  grid (24, 64).  Q additionally scaled by
// 0.125*log2(e) so attention can use exp2 directly with no per-score scaling.
// ---------------------------------------------------------------------------
__global__ __launch_bounds__(256, 2) void qkv_mma_kernel(
    const float* __restrict__ cos_f, const float* __restrict__ sin_f)
{
    extern __shared__ char dyn[];
    uint32_t sbase = (smem_u32(dyn) + 1023u) & ~1023u;
    const int tid = threadIdx.x, lane = tid & 31, warp = tid >> 5;
    const int wm = (warp & 3) * 32, wn = (warp >> 2) * 64;
    const int wsel = blockIdx.x >> 3;
    const int n0 = (blockIdx.x & 7) * 128;
    const int m0 = blockIdx.y * 128;
    const __half* B = (wsel == 0) ? g_whq : (wsel == 1) ? g_whk : g_whv;

    float acc[2][8][4];
    gemm_mainloop_f16(g_xh, B, m0, n0, sbase, acc);

    __half* dst = (wsel == 0) ? g_qh : (wsel == 1) ? g_kh : g_vh;
    const float qc = (wsel == 0) ? QSCALE_LOG : 1.0f;
    const int r0 = lane >> 2, cc = (lane & 3) * 2;
    #pragma unroll
    for (int mf = 0; mf < 2; mf++) {
        int m = m0 + wm + mf * 16 + r0;
        int s0 = m & 2047, bidx = m >> 11;
        #pragma unroll
        for (int nf = 0; nf < 8; nf++) {
            int n = n0 + wn + nf * 8 + cc;
            int h = n >> 6, d = n & 63;
            size_t a0 = ((size_t)(bidx * 16 + h) * 2048 + s0) * 64 + d;
            size_t a1 = a0 + 8 * 64;
            if (wsel < 2) {
                int fi = d >> 1;
                float c0v = cos_f[s0 * 32 + fi],       s0v = sin_f[s0 * 32 + fi];
                float c1v = cos_f[(s0 + 8) * 32 + fi], s1v = sin_f[(s0 + 8) * 32 + fi];
                float e0 = acc[mf][nf][0], o0 = acc[mf][nf][1];
                float e1 = acc[mf][nf][2], o1 = acc[mf][nf][3];
                *reinterpret_cast<uint32_t*>(&dst[a0]) =
                    packh2(qc * (e0 * c0v - o0 * s0v), qc * (e0 * s0v + o0 * c0v));
                *reinterpret_cast<uint32_t*>(&dst[a1]) =
                    packh2(qc * (e1 * c1v - o1 * s1v), qc * (e1 * s1v + o1 * c1v));
            } else {
                *reinterpret_cast<uint32_t*>(&dst[a0]) =
                    packh2(acc[mf][nf][0], acc[mf][nf][1]);
                *reinterpret_cast<uint32_t*>(&dst[a1]) =
                    packh2(acc[mf][nf][2], acc[mf][nf][3]);
            }
        }
    }
}

// ---------------------------------------------------------------------------
// Output projection: out(f32) = g_oh @ Wo^T.  grid (8, 64).
// ---------------------------------------------------------------------------
__global__ __launch_bounds__(256, 2) void oproj_mma_kernel(float* __restrict__ out)
{
    extern __shared__ char dyn[];
    uint32_t sbase = (smem_u32(dyn) + 1023u) & ~1023u;
    const int tid = threadIdx.x, lane = tid & 31, warp = tid >> 5;
    const int wm = (warp & 3) * 32, wn = (warp >> 2) * 64;
    const int n0 = blockIdx.x * 128;
    const int m0 = blockIdx.y * 128;

    float acc[2][8][4];
    gemm_mainloop_f16(g_oh, g_who, m0, n0, sbase, acc);

    const int r0 = lane >> 2, cc = (lane & 3) * 2;
    #pragma unroll
    for (int mf = 0; mf < 2; mf++) {
        int m = m0 + wm + mf * 16 + r0;
        #pragma unroll
        for (int nf = 0; nf < 8; nf++) {
            int n = n0 + wn + nf * 8 + cc;
            *reinterpret_cast<float2*>(&out[(size_t)m * 1024 + n]) =
                make_float2(acc[mf][nf][0], acc[mf][nf][1]);
            *reinterpret_cast<float2*>(&out[(size_t)(m + 8) * 1024 + n]) =
                make_float2(acc[mf][nf][2], acc[mf][nf][3]);
        }
    }
}

// ---------------------------------------------------------------------------
// Flash attention (R11 numerics): no-max softmax, f32 score accumulators,
// f16x2 exponentials, tensor-core row sums, warp-level skip of kv tiles that
// are entirely causally masked for this warp (exact: P==0 there).
// MASK predicate uses the warp's FIRST q row (q0+warp*16): any tile whose
// last kv exceeds it needs per-element masking.  (R13's bug: used last row.)
// Block 128q x 64kv, 8 warps, 3-stage cp.async, heavy-first.
// ---------------------------------------------------------------------------
__global__ __launch_bounds__(256, 2) void attn_mma_kernel()
{
    extern __shared__ char dyn[];
    uint32_t sbase = (smem_u32(dyn) + 1023u) & ~1023u;
    const uint32_t Qs = sbase, KV0 = sbase + 16384;   // 3 stages x 16KB (K8+V8)

    const int tid = threadIdx.x, lane = tid & 31, warp = tid >> 5;
    const int lr = lane & 7, lmat = lane >> 3;
    const int T = (int)gridDim.x - 1 - (int)blockIdx.x;   // heavy tiles first
    const int bh = blockIdx.y;
    const int q0 = T * 128;
    const __half* Qg = g_qh + (size_t)bh * 2048 * 64;
    const __half* Kg = g_kh + (size_t)bh * 2048 * 64;
    const __half* Vg = g_vh + (size_t)bh * 2048 * 64;

    const int krow = tid >> 2, kcb = (tid & 3) * 2;
    auto ISSUEKV = [&](int t) {
        uint32_t kb = KV0 + (t % 3) * 16384, vb = kb + 8192;
        #pragma unroll
        for (int j = 0; j < 2; j++) {
            uint32_t so = SWZ((uint32_t)(krow * 128 + (kcb + j) * 16));
            const size_t go = (size_t)(t * 64 + krow) * 64 + (kcb + j) * 8;
            cpa16(kb + so, Kg + go);
            cpa16(vb + so, Vg + go);
        }
        cp_commit();
    };

    // Q tile rides in the stage-0 commit group
    {
        const int qrow = tid >> 1, qcb = (tid & 1) * 4;
        #pragma unroll
        for (int j = 0; j < 4; j++)
            cpa16(Qs + SWZ((uint32_t)(qrow * 128 + (qcb + j) * 16)),
                  Qg + (size_t)(q0 + qrow) * 64 + (qcb + j) * 8);
    }
    ISSUEKV(0);
    ISSUEKV(1);
    cp_wait<1>();          // stage 0 (incl. Q) landed
    __syncthreads();

    // hoist Q fragments (loop-invariant)
    uint32_t qa[4][4];
    #pragma unroll
    for (int kk = 0; kk < 4; kk++) {
        int row = warp * 16 + lr + (lmat & 1) * 8;
        int ch  = kk * 2 + (lmat >> 1);
        ldm_x4(qa[kk], Qs + SWZ((uint32_t)(row * 128 + ch * 16)));
    }

    const int nt = 2 * T + 2;
    const int r0 = lane >> 2, cc = (lane & 3) * 2;
    const int qw0  = q0 + warp * 16;            // first q row owned by warp
    const int qg0  = qw0 + r0;
    const int qwmax = qw0 + 15;                 // last q row owned by warp
    const uint32_t ONESB[2] = {0x3C003C00u, 0x3C003C00u};   // ones B-frag (k16n8)
    float lacc[4] = {0.f, 0.f, 0.f, 0.f};                   // row sums via MMA
    float oacc[8][4];
    #pragma unroll
    for (int f = 0; f < 8; f++)
        #pragma unroll
        for (int r = 0; r < 4; r++) oacc[f][r] = 0.f;

    for (int t = 0; t < nt; t++) {
        if (t > 0) {
            if (t + 1 < nt) cp_wait<1>();
            else            cp_wait<0>();
            __syncthreads();
        }
        const uint32_t kb = KV0 + (t % 3) * 16384, vb = kb + 8192;
        const int kv0 = t * 64;

        if (kv0 <= qwmax) {   // warp-uniform skip of fully-masked 16x64 blocks
            // S' = Q' K^T   (already includes 0.125*log2e)
            float sacc[8][4];
            #pragma unroll
            for (int f = 0; f < 8; f++)
                #pragma unroll
                for (int r = 0; r < 4; r++) sacc[f][r] = 0.f;
            #pragma unroll
            for (int kk = 0; kk < 4; kk++) {
                const int c0 = kk * 2;
                #pragma unroll
                for (int q = 0; q < 4; q++) {
                    uint32_t kf[4];
                    int row = q * 16 + lr + (lmat >> 1) * 8;
                    int ch  = c0 + (lmat & 1);
                    ldm_x4(kf, kb + SWZ((uint32_t)(row * 128 + ch * 16)));
                    mma_f16(sacc[2 * q],     qa[kk], kf);
                    mma_f16(sacc[2 * q + 1], qa[kk], kf + 2);
                }
            }

            // causal mask: needed when any kv in tile exceeds the warp's
            // FIRST q row (kv0+63 > qw0)
            if (kv0 + 63 > qw0) {
                #pragma unroll
                for (int f = 0; f < 8; f++) {
                    int kvb = kv0 + f * 8 + cc;
                    #pragma unroll
                    for (int j = 0; j < 4; j++) {
                        int kvj = kvb + (j & 1);
                        int qi  = (j < 2) ? qg0 : (qg0 + 8);
                        if (kvj > qi) sacc[f][j] = -1e30f;
                    }
                }
            }

            // pack scores to f16x2 (satfinite: -1e30 -> -65504 -> exp -> 0),
            // then P = 2^s' with ONE MUFU op per two scores
            uint32_t pa[4][4];
            #pragma unroll
            for (int kk = 0; kk < 4; kk++) {
                pa[kk][0] = packh2s(sacc[2 * kk][0],     sacc[2 * kk][1]);
                pa[kk][1] = packh2s(sacc[2 * kk][2],     sacc[2 * kk][3]);
                pa[kk][2] = packh2s(sacc[2 * kk + 1][0], sacc[2 * kk + 1][1]);
                pa[kk][3] = packh2s(sacc[2 * kk + 1][2], sacc[2 * kk + 1][3]);
                #pragma unroll
                for (int r = 0; r < 4; r++) h2exp2(pa[kk][r]);
            }

            // O += P @ V, and l += P @ ones (row sums on the tensor pipe)
            #pragma unroll
            for (int kk = 0; kk < 4; kk++) {
                mma_f16(lacc, pa[kk], ONESB);
                #pragma unroll
                for (int q = 0; q < 4; q++) {
                    uint32_t vf[4];
                    int row = kk * 16 + lr + (lmat & 1) * 8;
                    int ch  = q * 2 + (lmat >> 1);
                    ldm_x4t(vf, vb + SWZ((uint32_t)(row * 128 + ch * 16)));
                    mma_f16(oacc[2 * q],     pa[kk], vf);
                    mma_f16(oacc[2 * q + 1], pa[kk], vf + 2);
                }
            }
        }

        if (t + 2 < nt) ISSUEKV(t + 2);
    }

    // epilogue: normalize by l (cols of lacc identical; [0]=row r0, [2]=r0+8)
    float inv0 = 1.f / lacc[0], inv1 = 1.f / lacc[2];
    const int b = bh >> 4, hh = bh & 15;
    #pragma unroll
    for (int f = 0; f < 8; f++) {
        int d = hh * 64 + f * 8 + cc;
        size_t a0 = ((size_t)b * 2048 + qg0) * 1024 + d;
        *reinterpret_cast<uint32_t*>(&g_oh[a0]) =
            packh2(oacc[f][0] * inv0, oacc[f][1] * inv0);
        *reinterpret_cast<uint32_t*>(&g_oh[a0 + 8 * 1024]) =
            packh2(oacc[f][2] * inv1, oacc[f][3] * inv1);
    }
}

// ---------------------------------------------------------------------------
extern "C" void kernel_launch(void* const* d_in, const int* in_sizes, int n_in,
                              void* d_out, int out_size) {
    const float* x     = (const float*)d_in[0];
    const float* cos_f = (const float*)d_in[1];
    const float* sin_f = (const float*)d_in[2];
    // d_in[3] = causal_mask: unused (mask synthesized analytically)
    const float* wq    = (const float*)d_in[4];
    const float* wk    = (const float*)d_in[5];
    const float* wv    = (const float*)d_in[6];
    const float* wo    = (const float*)d_in[7];
    float* out = (float*)d_out;

    const int GEMM_SMEM = 99328;   // 3 stages x 32KB + align slack
    const int ATTN_SMEM = 66560;   // Q 16KB + 3 x (K 8KB + V 8KB) + slack
    cudaFuncSetAttribute(qkv_mma_kernel,
                         cudaFuncAttributeMaxDynamicSharedMemorySize, GEMM_SMEM);
    cudaFuncSetAttribute(oproj_mma_kernel,
                         cudaFuncAttributeMaxDynamicSharedMemorySize, GEMM_SMEM);
    cudaFuncSetAttribute(attn_mma_kernel,
                         cudaFuncAttributeMaxDynamicSharedMemorySize, ATTN_SMEM);

    f2h_multi<<<12288, 256>>>(x, wq, wk, wv, wo);
    qkv_mma_kernel<<<dim3(24, 64), 256, GEMM_SMEM>>>(cos_f, sin_f);
    attn_mma_kernel<<<dim3(16, 64), 256, ATTN_SMEM>>>();
    oproj_mma_kernel<<<dim3(8, 64), 256, GEMM_SMEM>>>(out);
}

// round 15
// speedup vs baseline: 1.0152x; 1.0152x over previous
#include <cuda_runtime.h>
#include <cuda_fp16.h>
#include <cstdint>

#define SWZ(o) ((o) ^ (((o) >> 3) & 0x70))
// exp(s/8) = 2^(s * QSCALE_LOG):  folded into q at the QKV epilogue
#define QSCALE_LOG 0.18033688011112042f   // 0.125 * log2(e)

// fp16 staging / intermediate buffers
__device__ __align__(16) __half g_xh[8388608];    // X as half [8192][1024]
__device__ __align__(16) __half g_whq[1048576];
__device__ __align__(16) __half g_whk[1048576];
__device__ __align__(16) __half g_whv[1048576];
__device__ __align__(16) __half g_who[1048576];
__device__ __align__(16) __half g_qh[8388608];    // [B*H][2048][64]  (q pre-scaled)
__device__ __align__(16) __half g_kh[8388608];
__device__ __align__(16) __half g_vh[8388608];
__device__ __align__(16) __half g_oh[8388608];    // attn out [8192][1024]

// ---------------------------------------------------------------------------
// helpers
// ---------------------------------------------------------------------------
__device__ __forceinline__ uint32_t smem_u32(const void* p) {
    uint32_t a;
    asm("{ .reg .u64 t; cvta.to.shared.u64 t, %1; cvt.u32.u64 %0, t; }"
        : "=r"(a) : "l"(p));
    return a;
}
__device__ __forceinline__ void cpa16(uint32_t s, const void* g) {
    asm volatile("cp.async.cg.shared.global [%0], [%1], 16;"
                 :: "r"(s), "l"(g) : "memory");
}
__device__ __forceinline__ void cp_commit() {
    asm volatile("cp.async.commit_group;" ::: "memory");
}
template <int N>
__device__ __forceinline__ void cp_wait() {
    asm volatile("cp.async.wait_group %0;" :: "n"(N) : "memory");
}
__device__ __forceinline__ void ldm_x4(uint32_t* r, uint32_t addr) {
    asm volatile("ldmatrix.sync.aligned.m8n8.x4.shared.b16 {%0,%1,%2,%3}, [%4];"
                 : "=r"(r[0]), "=r"(r[1]), "=r"(r[2]), "=r"(r[3]) : "r"(addr));
}
__device__ __forceinline__ void ldm_x4t(uint32_t* r, uint32_t addr) {
    asm volatile("ldmatrix.sync.aligned.m8n8.x4.trans.shared.b16 {%0,%1,%2,%3}, [%4];"
                 : "=r"(r[0]), "=r"(r[1]), "=r"(r[2]), "=r"(r[3]) : "r"(addr));
}
// D(f32) += A(f16 m16k16) * B(f16 col-major k16n8)
__device__ __forceinline__ void mma_f16(float* c, const uint32_t* a, const uint32_t* b) {
    asm volatile(
        "mma.sync.aligned.m16n8k16.row.col.f32.f16.f16.f32 "
        "{%0,%1,%2,%3}, {%4,%5,%6,%7}, {%8,%9}, {%0,%1,%2,%3};"
        : "+f"(c[0]), "+f"(c[1]), "+f"(c[2]), "+f"(c[3])
        : "r"(a[0]), "r"(a[1]), "r"(a[2]), "r"(a[3]), "r"(b[0]), "r"(b[1]));
}
__device__ __forceinline__ uint32_t packh2(float a, float b) {
    __half2 h = __floats2half2_rn(a, b);
    return *reinterpret_cast<uint32_t*>(&h);
}
// saturating pack: clamps to +-65504 instead of producing inf
__device__ __forceinline__ uint32_t packh2s(float a, float b) {
    uint32_t r;
    asm("cvt.rn.satfinite.f16x2.f32 %0, %1, %2;" : "=r"(r) : "f"(b), "f"(a));
    return r;
}
// 2^x on both f16 halves (one MUFU op for two exps)
__device__ __forceinline__ void h2exp2(uint32_t& v) {
    asm("ex2.approx.f16x2 %0, %0;" : "+r"(v));
}

// ---------------------------------------------------------------------------
// f32 -> f16 pre-pass for X and the 4 weight matrices (one launch)
// ---------------------------------------------------------------------------
__global__ __launch_bounds__(256) void f2h_multi(
    const float* __restrict__ x,  const float* __restrict__ wq,
    const float* __restrict__ wk, const float* __restrict__ wv,
    const float* __restrict__ wo)
{
    int i = blockIdx.x * 256 + threadIdx.x;   // float4 index, total 3145728
    const float4* s;
    __half* d;
    int off;
    if (i < 2097152) { s = (const float4*)x; d = g_xh; off = i; }
    else {
        int r = i - 2097152;
        int w = r >> 18;
        off = r & 262143;
        s = (const float4*)(w == 0 ? wq : w == 1 ? wk : w == 2 ? wv : wo);
        d = (w == 0) ? g_whq : (w == 1) ? g_whk : (w == 2) ? g_whv : g_who;
    }
    float4 v = s[off];
    uint2 u;
    u.x = packh2(v.x, v.y);
    u.y = packh2(v.z, v.w);
    *reinterpret_cast<uint2*>(d + (size_t)off * 4) = u;
}

// ---------------------------------------------------------------------------
// f16 MMA GEMM mainloop v2: C[128,64] = A[128rows] * B[64rows]^T, BK=64,
// 3-stage cp.async (24KB/stage: A 16KB + B 8KB), one sync per k-iter,
// per-warp kk rotation.  8 warps = 4(m) x 2(n); warp tile 32x32 -> ~80 regs
// so THREE CTAs fit per SM (24 warps: the occupancy experiment).
// ---------------------------------------------------------------------------
__device__ __forceinline__ void gemm_mainloop_v2(
    const __half* __restrict__ A, const __half* __restrict__ B,
    int m0, int n0, uint32_t sbase, float (&acc)[2][4][4])
{
    const int tid = threadIdx.x, lane = tid & 31, warp = tid >> 5;
    const int lr = lane & 7, lmat = lane >> 3;
    const int wm = (warp & 3) * 32, wn = (warp >> 2) * 32;
    const int srow = tid >> 3, sch = tid & 7;
    const int krot = warp & 3;

    const __half* ga[4];
    const __half* gb[2];
    uint32_t swo[4];
    #pragma unroll
    for (int j = 0; j < 4; j++) {
        int row = srow + j * 32;
        ga[j] = A + (size_t)(m0 + row) * 1024 + sch * 8;
        swo[j] = SWZ((uint32_t)(row * 128 + sch * 16));
    }
    #pragma unroll
    for (int j = 0; j < 2; j++)
        gb[j] = B + (size_t)(n0 + srow + j * 32) * 1024 + sch * 8;

    #pragma unroll
    for (int a = 0; a < 2; a++)
        #pragma unroll
        for (int b = 0; b < 4; b++)
            #pragma unroll
            for (int r = 0; r < 4; r++) acc[a][b][r] = 0.f;

    auto ISSUE = [&](int s) {
        uint32_t ab = sbase + (s % 3) * 24576, bb = ab + 16384;
        #pragma unroll
        for (int j = 0; j < 4; j++)
            cpa16(ab + swo[j], ga[j] + s * 64);
        #pragma unroll
        for (int j = 0; j < 2; j++)
            cpa16(bb + swo[j], gb[j] + s * 64);
        cp_commit();
    };

    ISSUE(0); ISSUE(1);
    for (int i = 0; i < 16; i++) {
        if (i + 1 < 16) cp_wait<1>();
        else            cp_wait<0>();
        __syncthreads();
        if (i + 2 < 16) ISSUE(i + 2);
        uint32_t ab = sbase + (i % 3) * 24576, bb = ab + 16384;
        #pragma unroll
        for (int kk0 = 0; kk0 < 4; kk0++) {
            const int kk = (kk0 + krot) & 3;     // per-warp phase stagger
            const int c0 = kk * 2;
            uint32_t a[2][4];
            #pragma unroll
            for (int mf = 0; mf < 2; mf++) {
                int row = wm + mf * 16 + lr + (lmat & 1) * 8;
                int ch  = c0 + (lmat >> 1);
                ldm_x4(a[mf], ab + SWZ((uint32_t)(row * 128 + ch * 16)));
            }
            #pragma unroll
            for (int q = 0; q < 2; q++) {
                uint32_t bq[4];
                int row = wn + q * 16 + lr + (lmat >> 1) * 8;
                int ch  = c0 + (lmat & 1);
                ldm_x4(bq, bb + SWZ((uint32_t)(row * 128 + ch * 16)));
                #pragma unroll
                for (int mf = 0; mf < 2; mf++) {
                    mma_f16(acc[mf][2 * q],     a[mf], bq);
                    mma_f16(acc[mf][2 * q + 1], a[mf], bq + 2);
                }
            }
        }
    }
}

// ---------------------------------------------------------------------------
// QKV projection (+RoPE).  grid (48, 64): x -> wsel*16 + ntile(64-wide),
// y -> m tile.  Q additionally scaled by 0.125*log2(e).
// ---------------------------------------------------------------------------
__global__ __launch_bounds__(256, 3) void qkv_mma_kernel(
    const float* __restrict__ cos_f, const float* __restrict__ sin_f)
{
    extern __shared__ char dyn[];
    uint32_t sbase = (smem_u32(dyn) + 127u) & ~127u;
    const int tid = threadIdx.x, lane = tid & 31, warp = tid >> 5;
    const int wm = (warp & 3) * 32, wn = (warp >> 2) * 32;
    const int wsel = blockIdx.x >> 4;
    const int n0 = (blockIdx.x & 15) * 64;
    const int m0 = blockIdx.y * 128;
    const __half* B = (wsel == 0) ? g_whq : (wsel == 1) ? g_whk : g_whv;

    float acc[2][4][4];
    gemm_mainloop_v2(g_xh, B, m0, n0, sbase, acc);

    __half* dst = (wsel == 0) ? g_qh : (wsel == 1) ? g_kh : g_vh;
    const float qc = (wsel == 0) ? QSCALE_LOG : 1.0f;
    const int r0 = lane >> 2, cc = (lane & 3) * 2;
    #pragma unroll
    for (int mf = 0; mf < 2; mf++) {
        int m = m0 + wm + mf * 16 + r0;
        int s0 = m & 2047, bidx = m >> 11;
        #pragma unroll
        for (int nf = 0; nf < 4; nf++) {
            int n = n0 + wn + nf * 8 + cc;
            int h = n >> 6, d = n & 63;
            size_t a0 = ((size_t)(bidx * 16 + h) * 2048 + s0) * 64 + d;
            size_t a1 = a0 + 8 * 64;
            if (wsel < 2) {
                int fi = d >> 1;
                float c0v = cos_f[s0 * 32 + fi],       s0v = sin_f[s0 * 32 + fi];
                float c1v = cos_f[(s0 + 8) * 32 + fi], s1v = sin_f[(s0 + 8) * 32 + fi];
                float e0 = acc[mf][nf][0], o0 = acc[mf][nf][1];
                float e1 = acc[mf][nf][2], o1 = acc[mf][nf][3];
                *reinterpret_cast<uint32_t*>(&dst[a0]) =
                    packh2(qc * (e0 * c0v - o0 * s0v), qc * (e0 * s0v + o0 * c0v));
                *reinterpret_cast<uint32_t*>(&dst[a1]) =
                    packh2(qc * (e1 * c1v - o1 * s1v), qc * (e1 * s1v + o1 * c1v));
            } else {
                *reinterpret_cast<uint32_t*>(&dst[a0]) =
                    packh2(acc[mf][nf][0], acc[mf][nf][1]);
                *reinterpret_cast<uint32_t*>(&dst[a1]) =
                    packh2(acc[mf][nf][2], acc[mf][nf][3]);
            }
        }
    }
}

// ---------------------------------------------------------------------------
// Output projection: out(f32) = g_oh @ Wo^T.  grid (16, 64).
// ---------------------------------------------------------------------------
__global__ __launch_bounds__(256, 3) void oproj_mma_kernel(float* __restrict__ out)
{
    extern __shared__ char dyn[];
    uint32_t sbase = (smem_u32(dyn) + 127u) & ~127u;
    const int tid = threadIdx.x, lane = tid & 31, warp = tid >> 5;
    const int wm = (warp & 3) * 32, wn = (warp >> 2) * 32;
    const int n0 = blockIdx.x * 64;
    const int m0 = blockIdx.y * 128;

    float acc[2][4][4];
    gemm_mainloop_v2(g_oh, g_who, m0, n0, sbase, acc);

    const int r0 = lane >> 2, cc = (lane & 3) * 2;
    #pragma unroll
    for (int mf = 0; mf < 2; mf++) {
        int m = m0 + wm + mf * 16 + r0;
        #pragma unroll
        for (int nf = 0; nf < 4; nf++) {
            int n = n0 + wn + nf * 8 + cc;
            *reinterpret_cast<float2*>(&out[(size_t)m * 1024 + n]) =
                make_float2(acc[mf][nf][0], acc[mf][nf][1]);
            *reinterpret_cast<float2*>(&out[(size_t)(m + 8) * 1024 + n]) =
                make_float2(acc[mf][nf][2], acc[mf][nf][3]);
        }
    }
}

// ---------------------------------------------------------------------------
// Flash attention (R11-exact, the best-known config): no-max softmax, f32
// score accumulators, f16x2 exponentials, tensor-core row sums, no skip.
// Block 128q x 64kv, 8 warps, 3-stage cp.async, heavy-first.
// ---------------------------------------------------------------------------
__global__ __launch_bounds__(256, 2) void attn_mma_kernel()
{
    extern __shared__ char dyn[];
    uint32_t sbase = (smem_u32(dyn) + 1023u) & ~1023u;
    const uint32_t Qs = sbase, KV0 = sbase + 16384;   // 3 stages x 16KB (K8+V8)

    const int tid = threadIdx.x, lane = tid & 31, warp = tid >> 5;
    const int lr = lane & 7, lmat = lane >> 3;
    const int T = (int)gridDim.x - 1 - (int)blockIdx.x;   // heavy tiles first
    const int bh = blockIdx.y;
    const int q0 = T * 128;
    const __half* Qg = g_qh + (size_t)bh * 2048 * 64;
    const __half* Kg = g_kh + (size_t)bh * 2048 * 64;
    const __half* Vg = g_vh + (size_t)bh * 2048 * 64;

    const int krow = tid >> 2, kcb = (tid & 3) * 2;
    auto ISSUEKV = [&](int t) {
        uint32_t kb = KV0 + (t % 3) * 16384, vb = kb + 8192;
        #pragma unroll
        for (int j = 0; j < 2; j++) {
            uint32_t so = SWZ((uint32_t)(krow * 128 + (kcb + j) * 16));
            const size_t go = (size_t)(t * 64 + krow) * 64 + (kcb + j) * 8;
            cpa16(kb + so, Kg + go);
            cpa16(vb + so, Vg + go);
        }
        cp_commit();
    };

    // Q tile rides in the stage-0 commit group
    {
        const int qrow = tid >> 1, qcb = (tid & 1) * 4;
        #pragma unroll
        for (int j = 0; j < 4; j++)
            cpa16(Qs + SWZ((uint32_t)(qrow * 128 + (qcb + j) * 16)),
                  Qg + (size_t)(q0 + qrow) * 64 + (qcb + j) * 8);
    }
    ISSUEKV(0);
    ISSUEKV(1);
    cp_wait<1>();          // stage 0 (incl. Q) landed
    __syncthreads();

    // hoist Q fragments (loop-invariant)
    uint32_t qa[4][4];
    #pragma unroll
    for (int kk = 0; kk < 4; kk++) {
        int row = warp * 16 + lr + (lmat & 1) * 8;
        int ch  = kk * 2 + (lmat >> 1);
        ldm_x4(qa[kk], Qs + SWZ((uint32_t)(row * 128 + ch * 16)));
    }

    const int nt = 2 * T + 2;
    const int r0 = lane >> 2, cc = (lane & 3) * 2;
    const int qg0 = q0 + warp * 16 + r0;
    const uint32_t ONESB[2] = {0x3C003C00u, 0x3C003C00u};   // ones B-frag (k16n8)
    float lacc[4] = {0.f, 0.f, 0.f, 0.f};                   // row sums via MMA
    float oacc[8][4];
    #pragma unroll
    for (int f = 0; f < 8; f++)
        #pragma unroll
        for (int r = 0; r < 4; r++) oacc[f][r] = 0.f;

    for (int t = 0; t < nt; t++) {
        if (t > 0) {
            if (t + 1 < nt) cp_wait<1>();
            else            cp_wait<0>();
            __syncthreads();
        }
        const uint32_t kb = KV0 + (t % 3) * 16384, vb = kb + 8192;

        // S' = Q' K^T   (already includes 0.125*log2e)
        float sacc[8][4];
        #pragma unroll
        for (int f = 0; f < 8; f++)
            #pragma unroll
            for (int r = 0; r < 4; r++) sacc[f][r] = 0.f;
        #pragma unroll
        for (int kk = 0; kk < 4; kk++) {
            const int c0 = kk * 2;
            #pragma unroll
            for (int q = 0; q < 4; q++) {
                uint32_t kf[4];
                int row = q * 16 + lr + (lmat >> 1) * 8;
                int ch  = c0 + (lmat & 1);
                ldm_x4(kf, kb + SWZ((uint32_t)(row * 128 + ch * 16)));
                mma_f16(sacc[2 * q],     qa[kk], kf);
                mma_f16(sacc[2 * q + 1], qa[kk], kf + 2);
            }
        }

        // causal mask (boundary tiles only)
        const int kv0 = t * 64;
        if (kv0 + 63 > q0 + warp * 16) {
            #pragma unroll
            for (int f = 0; f < 8; f++) {
                int kvb = kv0 + f * 8 + cc;
                #pragma unroll
                for (int j = 0; j < 4; j++) {
                    int kvj = kvb + (j & 1);
                    int qi  = (j < 2) ? qg0 : (qg0 + 8);
                    if (kvj > qi) sacc[f][j] = -1e30f;
                }
            }
        }

        // pack scores to f16x2 (satfinite: -1e30 -> -65504 -> exp -> 0),
        // then P = 2^s' with ONE MUFU op per two scores
        uint32_t pa[4][4];
        #pragma unroll
        for (int kk = 0; kk < 4; kk++) {
            pa[kk][0] = packh2s(sacc[2 * kk][0],     sacc[2 * kk][1]);
            pa[kk][1] = packh2s(sacc[2 * kk][2],     sacc[2 * kk][3]);
            pa[kk][2] = packh2s(sacc[2 * kk + 1][0], sacc[2 * kk + 1][1]);
            pa[kk][3] = packh2s(sacc[2 * kk + 1][2], sacc[2 * kk + 1][3]);
            #pragma unroll
            for (int r = 0; r < 4; r++) h2exp2(pa[kk][r]);
        }

        // O += P @ V, and l += P @ ones (row sums on the tensor pipe)
        #pragma unroll
        for (int kk = 0; kk < 4; kk++) {
            mma_f16(lacc, pa[kk], ONESB);
            #pragma unroll
            for (int q = 0; q < 4; q++) {
                uint32_t vf[4];
                int row = kk * 16 + lr + (lmat & 1) * 8;
                int ch  = q * 2 + (lmat >> 1);
                ldm_x4t(vf, vb + SWZ((uint32_t)(row * 128 + ch * 16)));
                mma_f16(oacc[2 * q],     pa[kk], vf);
                mma_f16(oacc[2 * q + 1], pa[kk], vf + 2);
            }
        }

        if (t + 2 < nt) ISSUEKV(t + 2);
    }

    // epilogue: normalize by l (cols of lacc identical; [0]=row r0, [2]=r0+8)
    float inv0 = 1.f / lacc[0], inv1 = 1.f / lacc[2];
    const int b = bh >> 4, hh = bh & 15;
    #pragma unroll
    for (int f = 0; f < 8; f++) {
        int d = hh * 64 + f * 8 + cc;
        size_t a0 = ((size_t)b * 2048 + qg0) * 1024 + d;
        *reinterpret_cast<uint32_t*>(&g_oh[a0]) =
            packh2(oacc[f][0] * inv0, oacc[f][1] * inv0);
        *reinterpret_cast<uint32_t*>(&g_oh[a0 + 8 * 1024]) =
            packh2(oacc[f][2] * inv1, oacc[f][3] * inv1);
    }
}

// ---------------------------------------------------------------------------
extern "C" void kernel_launch(void* const* d_in, const int* in_sizes, int n_in,
                              void* d_out, int out_size) {
    const float* x     = (const float*)d_in[0];
    const float* cos_f = (const float*)d_in[1];
    const float* sin_f = (const float*)d_in[2];
    // d_in[3] = causal_mask: unused (mask synthesized analytically)
    const float* wq    = (const float*)d_in[4];
    const float* wk    = (const float*)d_in[5];
    const float* wv    = (const float*)d_in[6];
    const float* wo    = (const float*)d_in[7];
    float* out = (float*)d_out;

    const int GEMM_SMEM = 73856;   // 3 stages x 24KB + 128B align (3 CTAs/SM)
    const int ATTN_SMEM = 66560;   // Q 16KB + 3 x (K 8KB + V 8KB) + slack
    cudaFuncSetAttribute(qkv_mma_kernel,
                         cudaFuncAttributeMaxDynamicSharedMemorySize, GEMM_SMEM);
    cudaFuncSetAttribute(oproj_mma_kernel,
                         cudaFuncAttributeMaxDynamicSharedMemorySize, GEMM_SMEM);
    cudaFuncSetAttribute(attn_mma_kernel,
                         cudaFuncAttributeMaxDynamicSharedMemorySize, ATTN_SMEM);

    f2h_multi<<<12288, 256>>>(x, wq, wk, wv, wo);
    qkv_mma_kernel<<<dim3(48, 64), 256, GEMM_SMEM>>>(cos_f, sin_f);
    attn_mma_kernel<<<dim3(16, 64), 256, ATTN_SMEM>>>();
    oproj_mma_kernel<<<dim3(16, 64), 256, GEMM_SMEM>>>(out);
}

// round 16
// speedup vs baseline: 1.0263x; 1.0110x over previous
#include <cuda_runtime.h>
#include <cuda_fp16.h>
#include <cstdint>

#define SWZ(o) ((o) ^ (((o) >> 3) & 0x70))
// exp(s/8) = 2^(s * QSCALE_LOG):  folded into q at the QKV epilogue
#define QSCALE_LOG 0.18033688011112042f   // 0.125 * log2(e)

// fp16 staging / intermediate buffers
__device__ __align__(16) __half g_xh[8388608];    // X as half [8192][1024]
__device__ __align__(16) __half g_whq[1048576];
__device__ __align__(16) __half g_whk[1048576];
__device__ __align__(16) __half g_whv[1048576];
__device__ __align__(16) __half g_who[1048576];
__device__ __align__(16) __half g_qh[8388608];    // [B*H][2048][64]  (q pre-scaled)
__device__ __align__(16) __half g_kh[8388608];
__device__ __align__(16) __half g_vh[8388608];
__device__ __align__(16) __half g_oh[8388608];    // attn out [8192][1024]

// ---------------------------------------------------------------------------
// helpers
// ---------------------------------------------------------------------------
__device__ __forceinline__ uint32_t smem_u32(const void* p) {
    uint32_t a;
    asm("{ .reg .u64 t; cvta.to.shared.u64 t, %1; cvt.u32.u64 %0, t; }"
        : "=r"(a) : "l"(p));
    return a;
}
__device__ __forceinline__ void cpa16(uint32_t s, const void* g) {
    asm volatile("cp.async.cg.shared.global [%0], [%1], 16;"
                 :: "r"(s), "l"(g) : "memory");
}
__device__ __forceinline__ void cp_commit() {
    asm volatile("cp.async.commit_group;" ::: "memory");
}
template <int N>
__device__ __forceinline__ void cp_wait() {
    asm volatile("cp.async.wait_group %0;" :: "n"(N) : "memory");
}
__device__ __forceinline__ void ldm_x4(uint32_t* r, uint32_t addr) {
    asm volatile("ldmatrix.sync.aligned.m8n8.x4.shared.b16 {%0,%1,%2,%3}, [%4];"
                 : "=r"(r[0]), "=r"(r[1]), "=r"(r[2]), "=r"(r[3]) : "r"(addr));
}
__device__ __forceinline__ void ldm_x4t(uint32_t* r, uint32_t addr) {
    asm volatile("ldmatrix.sync.aligned.m8n8.x4.trans.shared.b16 {%0,%1,%2,%3}, [%4];"
                 : "=r"(r[0]), "=r"(r[1]), "=r"(r[2]), "=r"(r[3]) : "r"(addr));
}
// D(f32) += A(f16 m16k16) * B(f16 col-major k16n8)
__device__ __forceinline__ void mma_f16(float* c, const uint32_t* a, const uint32_t* b) {
    asm volatile(
        "mma.sync.aligned.m16n8k16.row.col.f32.f16.f16.f32 "
        "{%0,%1,%2,%3}, {%4,%5,%6,%7}, {%8,%9}, {%0,%1,%2,%3};"
        : "+f"(c[0]), "+f"(c[1]), "+f"(c[2]), "+f"(c[3])
        : "r"(a[0]), "r"(a[1]), "r"(a[2]), "r"(a[3]), "r"(b[0]), "r"(b[1]));
}
__device__ __forceinline__ uint32_t packh2(float a, float b) {
    __half2 h = __floats2half2_rn(a, b);
    return *reinterpret_cast<uint32_t*>(&h);
}
// saturating pack: clamps to +-65504 instead of producing inf
__device__ __forceinline__ uint32_t packh2s(float a, float b) {
    uint32_t r;
    asm("cvt.rn.satfinite.f16x2.f32 %0, %1, %2;" : "=r"(r) : "f"(b), "f"(a));
    return r;
}
// 2^x on both f16 halves (one MUFU op for two exps)
__device__ __forceinline__ void h2exp2(uint32_t& v) {
    asm("ex2.approx.f16x2 %0, %0;" : "+r"(v));
}

// ---------------------------------------------------------------------------
// f32 -> f16 pre-pass for X and the 4 weight matrices (one launch)
// ---------------------------------------------------------------------------
__global__ __launch_bounds__(256) void f2h_multi(
    const float* __restrict__ x,  const float* __restrict__ wq,
    const float* __restrict__ wk, const float* __restrict__ wv,
    const float* __restrict__ wo)
{
    int i = blockIdx.x * 256 + threadIdx.x;   // float4 index, total 3145728
    const float4* s;
    __half* d;
    int off;
    if (i < 2097152) { s = (const float4*)x; d = g_xh; off = i; }
    else {
        int r = i - 2097152;
        int w = r >> 18;
        off = r & 262143;
        s = (const float4*)(w == 0 ? wq : w == 1 ? wk : w == 2 ? wv : wo);
        d = (w == 0) ? g_whq : (w == 1) ? g_whk : (w == 2) ? g_whv : g_who;
    }
    float4 v = s[off];
    uint2 u;
    u.x = packh2(v.x, v.y);
    u.y = packh2(v.z, v.w);
    *reinterpret_cast<uint2*>(d + (size_t)off * 4) = u;
}

// ---------------------------------------------------------------------------
// GEMM mainloop v1 (R11): C[128,128] = A * B^T, BK=64, 3-stage cp.async
// (32KB/stage), warp tile 32x64, ~128 regs -> 2 CTAs/SM.  Best B-reuse;
// used for qkv (A = X is large, reuse matters).
// ---------------------------------------------------------------------------
__device__ __forceinline__ void gemm_mainloop_v1(
    const __half* __restrict__ A, const __half* __restrict__ B,
    int m0, int n0, uint32_t sbase, float (&acc)[2][8][4])
{
    const int tid = threadIdx.x, lane = tid & 31, warp = tid >> 5;
    const int lr = lane & 7, lmat = lane >> 3;
    const int wm = (warp & 3) * 32, wn = (warp >> 2) * 64;
    const int srow = tid >> 3, sch = tid & 7;
    const int krot = warp & 3;

    const __half* ga[4];
    const __half* gb[4];
    uint32_t swo[4];
    #pragma unroll
    for (int j = 0; j < 4; j++) {
        int row = srow + j * 32;
        ga[j] = A + (size_t)(m0 + row) * 1024 + sch * 8;
        gb[j] = B + (size_t)(n0 + row) * 1024 + sch * 8;
        swo[j] = SWZ((uint32_t)(row * 128 + sch * 16));
    }
    #pragma unroll
    for (int a = 0; a < 2; a++)
        #pragma unroll
        for (int b = 0; b < 8; b++)
            #pragma unroll
            for (int r = 0; r < 4; r++) acc[a][b][r] = 0.f;

    auto ISSUE = [&](int s) {
        uint32_t ab = sbase + (s % 3) * 32768, bb = ab + 16384;
        #pragma unroll
        for (int j = 0; j < 4; j++) {
            cpa16(ab + swo[j], ga[j] + s * 64);
            cpa16(bb + swo[j], gb[j] + s * 64);
        }
        cp_commit();
    };

    ISSUE(0); ISSUE(1);
    for (int i = 0; i < 16; i++) {
        if (i + 1 < 16) cp_wait<1>();
        else            cp_wait<0>();
        __syncthreads();
        if (i + 2 < 16) ISSUE(i + 2);
        uint32_t ab = sbase + (i % 3) * 32768, bb = ab + 16384;
        #pragma unroll
        for (int kk0 = 0; kk0 < 4; kk0++) {
            const int kk = (kk0 + krot) & 3;     // per-warp phase stagger
            const int c0 = kk * 2;
            uint32_t a[2][4];
            #pragma unroll
            for (int mf = 0; mf < 2; mf++) {
                int row = wm + mf * 16 + lr + (lmat & 1) * 8;
                int ch  = c0 + (lmat >> 1);
                ldm_x4(a[mf], ab + SWZ((uint32_t)(row * 128 + ch * 16)));
            }
            #pragma unroll
            for (int q = 0; q < 4; q++) {
                uint32_t bq[4];
                int row = wn + q * 16 + lr + (lmat >> 1) * 8;
                int ch  = c0 + (lmat & 1);
                ldm_x4(bq, bb + SWZ((uint32_t)(row * 128 + ch * 16)));
                #pragma unroll
                for (int mf = 0; mf < 2; mf++) {
                    mma_f16(acc[mf][2 * q],     a[mf], bq);
                    mma_f16(acc[mf][2 * q + 1], a[mf], bq + 2);
                }
            }
        }
    }
}

// ---------------------------------------------------------------------------
// GEMM mainloop v2 (R15): C[128,64], BK=64, 3-stage cp.async (24KB/stage),
// warp tile 32x32, ~80 regs -> 3 CTAs/SM.  Higher occupancy; used for oproj
// (measured 50.2us vs 53.4 with v1).
// ---------------------------------------------------------------------------
__device__ __forceinline__ void gemm_mainloop_v2(
    const __half* __restrict__ A, const __half* __restrict__ B,
    int m0, int n0, uint32_t sbase, float (&acc)[2][4][4])
{
    const int tid = threadIdx.x, lane = tid & 31, warp = tid >> 5;
    const int lr = lane & 7, lmat = lane >> 3;
    const int wm = (warp & 3) * 32, wn = (warp >> 2) * 32;
    const int srow = tid >> 3, sch = tid & 7;
    const int krot = warp & 3;

    const __half* ga[4];
    const __half* gb[2];
    uint32_t swo[4];
    #pragma unroll
    for (int j = 0; j < 4; j++) {
        int row = srow + j * 32;
        ga[j] = A + (size_t)(m0 + row) * 1024 + sch * 8;
        swo[j] = SWZ((uint32_t)(row * 128 + sch * 16));
    }
    #pragma unroll
    for (int j = 0; j < 2; j++)
        gb[j] = B + (size_t)(n0 + srow + j * 32) * 1024 + sch * 8;

    #pragma unroll
    for (int a = 0; a < 2; a++)
        #pragma unroll
        for (int b = 0; b < 4; b++)
            #pragma unroll
            for (int r = 0; r < 4; r++) acc[a][b][r] = 0.f;

    auto ISSUE = [&](int s) {
        uint32_t ab = sbase + (s % 3) * 24576, bb = ab + 16384;
        #pragma unroll
        for (int j = 0; j < 4; j++)
            cpa16(ab + swo[j], ga[j] + s * 64);
        #pragma unroll
        for (int j = 0; j < 2; j++)
            cpa16(bb + swo[j], gb[j] + s * 64);
        cp_commit();
    };

    ISSUE(0); ISSUE(1);
    for (int i = 0; i < 16; i++) {
        if (i + 1 < 16) cp_wait<1>();
        else            cp_wait<0>();
        __syncthreads();
        if (i + 2 < 16) ISSUE(i + 2);
        uint32_t ab = sbase + (i % 3) * 24576, bb = ab + 16384;
        #pragma unroll
        for (int kk0 = 0; kk0 < 4; kk0++) {
            const int kk = (kk0 + krot) & 3;     // per-warp phase stagger
            const int c0 = kk * 2;
            uint32_t a[2][4];
            #pragma unroll
            for (int mf = 0; mf < 2; mf++) {
                int row = wm + mf * 16 + lr + (lmat & 1) * 8;
                int ch  = c0 + (lmat >> 1);
                ldm_x4(a[mf], ab + SWZ((uint32_t)(row * 128 + ch * 16)));
            }
            #pragma unroll
            for (int q = 0; q < 2; q++) {
                uint32_t bq[4];
                int row = wn + q * 16 + lr + (lmat >> 1) * 8;
                int ch  = c0 + (lmat & 1);
                ldm_x4(bq, bb + SWZ((uint32_t)(row * 128 + ch * 16)));
                #pragma unroll
                for (int mf = 0; mf < 2; mf++) {
                    mma_f16(acc[mf][2 * q],     a[mf], bq);
                    mma_f16(acc[mf][2 * q + 1], a[mf], bq + 2);
                }
            }
        }
    }
}

// ---------------------------------------------------------------------------
// QKV projection (+RoPE), v1 mainloop.  grid (24, 64): x -> wsel*8 + ntile,
// y -> m tile.  Q additionally scaled by 0.125*log2(e).
// ---------------------------------------------------------------------------
__global__ __launch_bounds__(256, 2) void qkv_mma_kernel(
    const float* __restrict__ cos_f, const float* __restrict__ sin_f)
{
    extern __shared__ char dyn[];
    uint32_t sbase = (smem_u32(dyn) + 1023u) & ~1023u;
    const int tid = threadIdx.x, lane = tid & 31, warp = tid >> 5;
    const int wm = (warp & 3) * 32, wn = (warp >> 2) * 64;
    const int wsel = blockIdx.x >> 3;
    const int n0 = (blockIdx.x & 7) * 128;
    const int m0 = blockIdx.y * 128;
    const __half* B = (wsel == 0) ? g_whq : (wsel == 1) ? g_whk : g_whv;

    float acc[2][8][4];
    gemm_mainloop_v1(g_xh, B, m0, n0, sbase, acc);

    __half* dst = (wsel == 0) ? g_qh : (wsel == 1) ? g_kh : g_vh;
    const float qc = (wsel == 0) ? QSCALE_LOG : 1.0f;
    const int r0 = lane >> 2, cc = (lane & 3) * 2;
    #pragma unroll
    for (int mf = 0; mf < 2; mf++) {
        int m = m0 + wm + mf * 16 + r0;
        int s0 = m & 2047, bidx = m >> 11;
        #pragma unroll
        for (int nf = 0; nf < 8; nf++) {
            int n = n0 + wn + nf * 8 + cc;
            int h = n >> 6, d = n & 63;
            size_t a0 = ((size_t)(bidx * 16 + h) * 2048 + s0) * 64 + d;
            size_t a1 = a0 + 8 * 64;
            if (wsel < 2) {
                int fi = d >> 1;
                float c0v = cos_f[s0 * 32 + fi],       s0v = sin_f[s0 * 32 + fi];
                float c1v = cos_f[(s0 + 8) * 32 + fi], s1v = sin_f[(s0 + 8) * 32 + fi];
                float e0 = acc[mf][nf][0], o0 = acc[mf][nf][1];
                float e1 = acc[mf][nf][2], o1 = acc[mf][nf][3];
                *reinterpret_cast<uint32_t*>(&dst[a0]) =
                    packh2(qc * (e0 * c0v - o0 * s0v), qc * (e0 * s0v + o0 * c0v));
                *reinterpret_cast<uint32_t*>(&dst[a1]) =
                    packh2(qc * (e1 * c1v - o1 * s1v), qc * (e1 * s1v + o1 * c1v));
            } else {
                *reinterpret_cast<uint32_t*>(&dst[a0]) =
                    packh2(acc[mf][nf][0], acc[mf][nf][1]);
                *reinterpret_cast<uint32_t*>(&dst[a1]) =
                    packh2(acc[mf][nf][2], acc[mf][nf][3]);
            }
        }
    }
}

// ---------------------------------------------------------------------------
// Output projection, v2 mainloop (3 CTAs/SM): out(f32) = g_oh @ Wo^T.
// grid (16, 64).
// ---------------------------------------------------------------------------
__global__ __launch_bounds__(256, 3) void oproj_mma_kernel(float* __restrict__ out)
{
    extern __shared__ char dyn[];
    uint32_t sbase = (smem_u32(dyn) + 127u) & ~127u;
    const int tid = threadIdx.x, lane = tid & 31, warp = tid >> 5;
    const int wm = (warp & 3) * 32, wn = (warp >> 2) * 32;
    const int n0 = blockIdx.x * 64;
    const int m0 = blockIdx.y * 128;

    float acc[2][4][4];
    gemm_mainloop_v2(g_oh, g_who, m0, n0, sbase, acc);

    const int r0 = lane >> 2, cc = (lane & 3) * 2;
    #pragma unroll
    for (int mf = 0; mf < 2; mf++) {
        int m = m0 + wm + mf * 16 + r0;
        #pragma unroll
        for (int nf = 0; nf < 4; nf++) {
            int n = n0 + wn + nf * 8 + cc;
            *reinterpret_cast<float2*>(&out[(size_t)m * 1024 + n]) =
                make_float2(acc[mf][nf][0], acc[mf][nf][1]);
            *reinterpret_cast<float2*>(&out[(size_t)(m + 8) * 1024 + n]) =
                make_float2(acc[mf][nf][2], acc[mf][nf][3]);
        }
    }
}

// ---------------------------------------------------------------------------
// Flash attention (R11-exact, best-known): no-max softmax, f32 score accs,
// f16x2 exponentials, tensor-core row sums.  Block 128q x 64kv, 8 warps,
// 3-stage cp.async, heavy-first.
// ---------------------------------------------------------------------------
__global__ __launch_bounds__(256, 2) void attn_mma_kernel()
{
    extern __shared__ char dyn[];
    uint32_t sbase = (smem_u32(dyn) + 1023u) & ~1023u;
    const uint32_t Qs = sbase, KV0 = sbase + 16384;   // 3 stages x 16KB (K8+V8)

    const int tid = threadIdx.x, lane = tid & 31, warp = tid >> 5;
    const int lr = lane & 7, lmat = lane >> 3;
    const int T = (int)gridDim.x - 1 - (int)blockIdx.x;   // heavy tiles first
    const int bh = blockIdx.y;
    const int q0 = T * 128;
    const __half* Qg = g_qh + (size_t)bh * 2048 * 64;
    const __half* Kg = g_kh + (size_t)bh * 2048 * 64;
    const __half* Vg = g_vh + (size_t)bh * 2048 * 64;

    const int krow = tid >> 2, kcb = (tid & 3) * 2;
    auto ISSUEKV = [&](int t) {
        uint32_t kb = KV0 + (t % 3) * 16384, vb = kb + 8192;
        #pragma unroll
        for (int j = 0; j < 2; j++) {
            uint32_t so = SWZ((uint32_t)(krow * 128 + (kcb + j) * 16));
            const size_t go = (size_t)(t * 64 + krow) * 64 + (kcb + j) * 8;
            cpa16(kb + so, Kg + go);
            cpa16(vb + so, Vg + go);
        }
        cp_commit();
    };

    // Q tile rides in the stage-0 commit group
    {
        const int qrow = tid >> 1, qcb = (tid & 1) * 4;
        #pragma unroll
        for (int j = 0; j < 4; j++)
            cpa16(Qs + SWZ((uint32_t)(qrow * 128 + (qcb + j) * 16)),
                  Qg + (size_t)(q0 + qrow) * 64 + (qcb + j) * 8);
    }
    ISSUEKV(0);
    ISSUEKV(1);
    cp_wait<1>();          // stage 0 (incl. Q) landed
    __syncthreads();

    // hoist Q fragments (loop-invariant)
    uint32_t qa[4][4];
    #pragma unroll
    for (int kk = 0; kk < 4; kk++) {
        int row = warp * 16 + lr + (lmat & 1) * 8;
        int ch  = kk * 2 + (lmat >> 1);
        ldm_x4(qa[kk], Qs + SWZ((uint32_t)(row * 128 + ch * 16)));
    }

    const int nt = 2 * T + 2;
    const int r0 = lane >> 2, cc = (lane & 3) * 2;
    const int qg0 = q0 + warp * 16 + r0;
    const uint32_t ONESB[2] = {0x3C003C00u, 0x3C003C00u};   // ones B-frag (k16n8)
    float lacc[4] = {0.f, 0.f, 0.f, 0.f};                   // row sums via MMA
    float oacc[8][4];
    #pragma unroll
    for (int f = 0; f < 8; f++)
        #pragma unroll
        for (int r = 0; r < 4; r++) oacc[f][r] = 0.f;

    for (int t = 0; t < nt; t++) {
        if (t > 0) {
            if (t + 1 < nt) cp_wait<1>();
            else            cp_wait<0>();
            __syncthreads();
        }
        const uint32_t kb = KV0 + (t % 3) * 16384, vb = kb + 8192;

        // S' = Q' K^T   (already includes 0.125*log2e)
        float sacc[8][4];
        #pragma unroll
        for (int f = 0; f < 8; f++)
            #pragma unroll
            for (int r = 0; r < 4; r++) sacc[f][r] = 0.f;
        #pragma unroll
        for (int kk = 0; kk < 4; kk++) {
            const int c0 = kk * 2;
            #pragma unroll
            for (int q = 0; q < 4; q++) {
                uint32_t kf[4];
                int row = q * 16 + lr + (lmat >> 1) * 8;
                int ch  = c0 + (lmat & 1);
                ldm_x4(kf, kb + SWZ((uint32_t)(row * 128 + ch * 16)));
                mma_f16(sacc[2 * q],     qa[kk], kf);
                mma_f16(sacc[2 * q + 1], qa[kk], kf + 2);
            }
        }

        // causal mask (boundary tiles only)
        const int kv0 = t * 64;
        if (kv0 + 63 > q0 + warp * 16) {
            #pragma unroll
            for (int f = 0; f < 8; f++) {
                int kvb = kv0 + f * 8 + cc;
                #pragma unroll
                for (int j = 0; j < 4; j++) {
                    int kvj = kvb + (j & 1);
                    int qi  = (j < 2) ? qg0 : (qg0 + 8);
                    if (kvj > qi) sacc[f][j] = -1e30f;
                }
            }
        }

        // pack scores to f16x2 (satfinite: -1e30 -> -65504 -> exp -> 0),
        // then P = 2^s' with ONE MUFU op per two scores
        uint32_t pa[4][4];
        #pragma unroll
        for (int kk = 0; kk < 4; kk++) {
            pa[kk][0] = packh2s(sacc[2 * kk][0],     sacc[2 * kk][1]);
            pa[kk][1] = packh2s(sacc[2 * kk][2],     sacc[2 * kk][3]);
            pa[kk][2] = packh2s(sacc[2 * kk + 1][0], sacc[2 * kk + 1][1]);
            pa[kk][3] = packh2s(sacc[2 * kk + 1][2], sacc[2 * kk + 1][3]);
            #pragma unroll
            for (int r = 0; r < 4; r++) h2exp2(pa[kk][r]);
        }

        // O += P @ V, and l += P @ ones (row sums on the tensor pipe)
        #pragma unroll
        for (int kk = 0; kk < 4; kk++) {
            mma_f16(lacc, pa[kk], ONESB);
            #pragma unroll
            for (int q = 0; q < 4; q++) {
                uint32_t vf[4];
                int row = kk * 16 + lr + (lmat & 1) * 8;
                int ch  = q * 2 + (lmat >> 1);
                ldm_x4t(vf, vb + SWZ((uint32_t)(row * 128 + ch * 16)));
                mma_f16(oacc[2 * q],     pa[kk], vf);
                mma_f16(oacc[2 * q + 1], pa[kk], vf + 2);
            }
        }

        if (t + 2 < nt) ISSUEKV(t + 2);
    }

    // epilogue: normalize by l (cols of lacc identical; [0]=row r0, [2]=r0+8)
    float inv0 = 1.f / lacc[0], inv1 = 1.f / lacc[2];
    const int b = bh >> 4, hh = bh & 15;
    #pragma unroll
    for (int f = 0; f < 8; f++) {
        int d = hh * 64 + f * 8 + cc;
        size_t a0 = ((size_t)b * 2048 + qg0) * 1024 + d;
        *reinterpret_cast<uint32_t*>(&g_oh[a0]) =
            packh2(oacc[f][0] * inv0, oacc[f][1] * inv0);
        *reinterpret_cast<uint32_t*>(&g_oh[a0 + 8 * 1024]) =
            packh2(oacc[f][2] * inv1, oacc[f][3] * inv1);
    }
}

// ---------------------------------------------------------------------------
extern "C" void kernel_launch(void* const* d_in, const int* in_sizes, int n_in,
                              void* d_out, int out_size) {
    const float* x     = (const float*)d_in[0];
    const float* cos_f = (const float*)d_in[1];
    const float* sin_f = (const float*)d_in[2];
    // d_in[3] = causal_mask: unused (mask synthesized analytically)
    const float* wq    = (const float*)d_in[4];
    const float* wk    = (const float*)d_in[5];
    const float* wv    = (const float*)d_in[6];
    const float* wo    = (const float*)d_in[7];
    float* out = (float*)d_out;

    const int QKV_SMEM   = 99328;   // v1: 3 stages x 32KB + align slack
    const int OPROJ_SMEM = 73856;   // v2: 3 stages x 24KB + 128B align (3 CTA/SM)
    const int ATTN_SMEM  = 66560;   // Q 16KB + 3 x (K 8KB + V 8KB) + slack
    cudaFuncSetAttribute(qkv_mma_kernel,
                         cudaFuncAttributeMaxDynamicSharedMemorySize, QKV_SMEM);
    cudaFuncSetAttribute(oproj_mma_kernel,
                         cudaFuncAttributeMaxDynamicSharedMemorySize, OPROJ_SMEM);
    cudaFuncSetAttribute(attn_mma_kernel,
                         cudaFuncAttributeMaxDynamicSharedMemorySize, ATTN_SMEM);

    f2h_multi<<<12288, 256>>>(x, wq, wk, wv, wo);
    qkv_mma_kernel<<<dim3(24, 64), 256, QKV_SMEM>>>(cos_f, sin_f);
    attn_mma_kernel<<<dim3(16, 64), 256, ATTN_SMEM>>>();
    oproj_mma_kernel<<<dim3(16, 64), 256, OPROJ_SMEM>>>(out);
}